// round 5
// baseline (speedup 1.0000x reference)
#include <cuda_runtime.h>
#include <cuda_bf16.h>

#define NROWS    8192
#define NF       1024
#define NTHREADS 256
#define NBLOCKS  512   // 512 blocks * 8 warps * 2 rows/warp = 8192 rows

__global__ __launch_bounds__(NTHREADS)
void kan_fused5(const float* __restrict__ x,
                const float* __restrict__ lnw,
                const float* __restrict__ lnb,
                const float* __restrict__ sw,
                const float* __restrict__ bw,
                const float* __restrict__ grid,
                float* __restrict__ out)
{
    // 11 swizzled planes of 1024 floats:
    //   planes 0..7  : spline coeff i, pre-scaled by 1/6
    //   plane  8     : lnw * inv_h
    //   plane  9     : (lnb - g0) * inv_h
    //   plane 10     : bw
    // Feature f = i*128 + 4*lane + c  is stored at
    //   (f&3)<<8 | (f>>7)<<5 | ((f>>2)&31)  =  c*256 + i*32 + lane
    // -> every tap/param LDS has bank = lane: conflict-free even with
    //    divergent plane indices.
    __shared__ float s_tab[11 * NF];

    const int tid  = threadIdx.x;
    const int wid  = tid >> 5;
    const int lane = tid & 31;

    const float g0    = grid[0];
    const float g11   = grid[11];
    const float inv_h = 11.0f / (g11 - g0);
    const float h     = (g11 - g0) * (1.0f / 11.0f);

    for (int f = tid; f < NF; f += NTHREADS) {
        float4 a = *reinterpret_cast<const float4*>(sw + f * 8);
        float4 b = *reinterpret_cast<const float4*>(sw + f * 8 + 4);
        const int base = ((f & 3) << 8) | ((f >> 7) << 5) | ((f >> 2) & 31);
        s_tab[0 * NF + base] = a.x * (1.0f/6.0f);
        s_tab[1 * NF + base] = a.y * (1.0f/6.0f);
        s_tab[2 * NF + base] = a.z * (1.0f/6.0f);
        s_tab[3 * NF + base] = a.w * (1.0f/6.0f);
        s_tab[4 * NF + base] = b.x * (1.0f/6.0f);
        s_tab[5 * NF + base] = b.y * (1.0f/6.0f);
        s_tab[6 * NF + base] = b.z * (1.0f/6.0f);
        s_tab[7 * NF + base] = b.w * (1.0f/6.0f);
        s_tab[8 * NF + base] = lnw[f] * inv_h;
        s_tab[9 * NF + base] = (lnb[f] - g0) * inv_h;
        s_tab[10 * NF + base] = bw[f];
    }
    __syncthreads();   // the only barrier in the kernel

    const int gwarp = blockIdx.x * 8 + wid;   // 0..4095

    #pragma unroll
    for (int r = 0; r < 2; r++) {
        const int row = gwarp + r * 4096;
        const float4* xr = reinterpret_cast<const float4*>(x + (size_t)row * NF);

        // Load full row: lane owns features i*128 + 4*lane + c
        float v[8][4];
        float s0 = 0.f, s1 = 0.f, q0 = 0.f, q1 = 0.f;
        #pragma unroll
        for (int i = 0; i < 8; i++) {
            float4 t = xr[i * 32 + lane];
            v[i][0] = t.x; v[i][1] = t.y; v[i][2] = t.z; v[i][3] = t.w;
            s0 += t.x + t.y;
            s1 += t.z + t.w;
            q0 = fmaf(t.x, t.x, fmaf(t.y, t.y, q0));
            q1 = fmaf(t.z, t.z, fmaf(t.w, t.w, q1));
        }
        float sum = s0 + s1;
        float sq  = q0 + q1;

        // Pure in-warp reduction: no block barrier, warps fully decoupled
        #pragma unroll
        for (int off = 16; off; off >>= 1) {
            sum += __shfl_xor_sync(0xffffffffu, sum, off);
            sq  += __shfl_xor_sync(0xffffffffu, sq,  off);
        }

        const float mu   = sum * (1.0f / NF);
        const float rstd = rsqrtf(sq * (1.0f / NF) - mu * mu + 1e-5f);

        float4* orow = reinterpret_cast<float4*>(out + (size_t)row * NF);

        #pragma unroll
        for (int i = 0; i < 8; i++) {
            const float* tb = s_tab + (i << 5) + lane;
            float4 res;
            float* resp = &res.x;

            #pragma unroll
            for (int c = 0; c < 4; c++) {
                const float Ac = tb[(8 << 10) + (c << 8)];
                const float Gc = tb[(9 << 10) + (c << 8)];
                const float Wc = tb[(10 << 10) + (c << 8)];

                const float xn = fmaf((v[i][c] - mu) * rstd, Ac, Gc); // knot units
                const float n  = fmaf(xn, h, g0);                     // normed

                const float fj = floorf(xn);
                const int   j  = (int)fj;
                const float t  = xn - fj;
                const float u  = 1.0f - t;
                const float t2 = t * t;
                const float B0 = u * u * u;
                const float B1 = fmaf(fmaf(3.0f, t, -6.0f), t2, 4.0f);
                const float B3 = t2 * t;
                const float B2 = 6.0f - B0 - B1 - B3;

                const int i0 = j - 3;
                const float* wf = tb + (c << 8);
                float s = 0.0f;
                if ((unsigned)(i0    ) < 8u) s = fmaf(B0, wf[(i0    ) << 10], s);
                if ((unsigned)(i0 + 1) < 8u) s = fmaf(B1, wf[(i0 + 1) << 10], s);
                if ((unsigned)(i0 + 2) < 8u) s = fmaf(B2, wf[(i0 + 2) << 10], s);
                if ((unsigned)(i0 + 3) < 8u) s = fmaf(B3, wf[(i0 + 3) << 10], s);

                const float sil = __fdividef(n, 1.0f + __expf(-n));
                resp[c] = fmaf(Wc, sil, s);
            }

            orow[i * 32 + lane] = res;
        }
    }
}

extern "C" void kernel_launch(void* const* d_in, const int* in_sizes, int n_in,
                              void* d_out, int out_size)
{
    const float* x    = (const float*)d_in[0];
    const float* lnw  = (const float*)d_in[1];
    const float* lnb  = (const float*)d_in[2];
    const float* sw   = (const float*)d_in[3];
    const float* bw   = (const float*)d_in[4];
    const float* grid = (const float*)d_in[5];
    float* out = (float*)d_out;

    kan_fused5<<<NBLOCKS, NTHREADS>>>(x, lnw, lnb, sw, bw, grid, out);
}

// round 6
// speedup vs baseline: 1.8923x; 1.8923x over previous
#include <cuda_runtime.h>
#include <cuda_bf16.h>

#define NROWS    8192
#define NF       1024
#define NTHREADS 256
#define NBLOCKS  1024
#define RPB      (NROWS / NBLOCKS)   // 8 rows per block

__global__ __launch_bounds__(NTHREADS)
void kan_fused6(const float* __restrict__ x,
                const float* __restrict__ lnw,
                const float* __restrict__ lnb,
                const float* __restrict__ sw,
                const float* __restrict__ bw,
                const float* __restrict__ grid,
                float* __restrict__ out)
{
    // Swizzled transposed planes: coeff i of feature f at i*1024 + (f&3)*256 + (f>>2).
    // Thread tid owns features 4*tid+c -> tap addr = i*1024 + c*256 + tid,
    // bank = tid mod 32 = lane: conflict-free under divergent plane index.
    __shared__ float  s_swT[8 * NF];
    __shared__ float2 s_red[2][8];     // [parity][warp] = {sum, sumsq}

    const int tid  = threadIdx.x;
    const int wid  = tid >> 5;
    const int lane = tid & 31;

    for (int f = tid; f < NF; f += NTHREADS) {
        float4 a = *reinterpret_cast<const float4*>(sw + f * 8);
        float4 b = *reinterpret_cast<const float4*>(sw + f * 8 + 4);
        const int base = ((f & 3) << 8) + (f >> 2);
        s_swT[0 * NF + base] = a.x * (1.0f/6.0f);
        s_swT[1 * NF + base] = a.y * (1.0f/6.0f);
        s_swT[2 * NF + base] = a.z * (1.0f/6.0f);
        s_swT[3 * NF + base] = a.w * (1.0f/6.0f);
        s_swT[4 * NF + base] = b.x * (1.0f/6.0f);
        s_swT[5 * NF + base] = b.y * (1.0f/6.0f);
        s_swT[6 * NF + base] = b.z * (1.0f/6.0f);
        s_swT[7 * NF + base] = b.w * (1.0f/6.0f);
    }

    const float g0    = grid[0];
    const float g11   = grid[11];
    const float inv_h = 11.0f / (g11 - g0);
    const float h     = (g11 - g0) * (1.0f / 11.0f);

    const float4 w4 = *reinterpret_cast<const float4*>(lnw + 4 * tid);
    const float4 b4 = *reinterpret_cast<const float4*>(lnb + 4 * tid);
    const float4 s4 = *reinterpret_cast<const float4*>(bw  + 4 * tid);
    float A[4], G[4], W[4];
    A[0] = w4.x * inv_h; A[1] = w4.y * inv_h; A[2] = w4.z * inv_h; A[3] = w4.w * inv_h;
    G[0] = (b4.x - g0) * inv_h; G[1] = (b4.y - g0) * inv_h;
    G[2] = (b4.z - g0) * inv_h; G[3] = (b4.w - g0) * inv_h;
    W[0] = s4.x; W[1] = s4.y; W[2] = s4.z; W[3] = s4.w;

    __syncthreads();

    const size_t col = 4 * tid;
    float4 cur = *reinterpret_cast<const float4*>(
                     x + (size_t)blockIdx.x * NF + col);

    int par = 0;
    #pragma unroll
    for (int k = 0; k < RPB; k++, par ^= 1) {
        const int row = blockIdx.x + k * NBLOCKS;

        // Prefetch next row: LDG in flight across this row's reduce+compute
        float4 nxt;
        if (k + 1 < RPB)
            nxt = *reinterpret_cast<const float4*>(
                      x + (size_t)(row + NBLOCKS) * NF + col);

        const float v[4] = {cur.x, cur.y, cur.z, cur.w};
        float sum = (v[0] + v[1]) + (v[2] + v[3]);
        float sq  = fmaf(v[0], v[0], v[1] * v[1]) +
                    fmaf(v[2], v[2], v[3] * v[3]);

        #pragma unroll
        for (int off = 16; off; off >>= 1) {
            sum += __shfl_xor_sync(0xffffffffu, sum, off);
            sq  += __shfl_xor_sync(0xffffffffu, sq,  off);
        }
        if (lane == 0) s_red[par][wid] = make_float2(sum, sq);
        __syncthreads();   // single barrier per row (parity double-buffer)

        float tot = 0.0f, tot2 = 0.0f;
        #pragma unroll
        for (int i = 0; i < 8; i++) {
            const float2 p = s_red[par][i];   // broadcast LDS.64
            tot += p.x; tot2 += p.y;
        }

        const float mu   = tot * (1.0f / NF);
        const float rstd = rsqrtf(tot2 * (1.0f / NF) - mu * mu + 1e-5f);

        float4 res;
        float* resp = &res.x;

        #pragma unroll
        for (int c = 0; c < 4; c++) {
            const float xn = fmaf((v[c] - mu) * rstd, A[c], G[c]); // knot units
            const float n  = fmaf(xn, h, g0);                      // normed

            const float fj = floorf(xn);
            const int   j  = (int)fj;
            const float t  = xn - fj;
            const float u  = 1.0f - t;
            const float t2 = t * t;
            const float B0 = u * u * u;
            const float B1 = fmaf(fmaf(3.0f, t, -6.0f), t2, 4.0f);
            const float B3 = t2 * t;
            const float B2 = 6.0f - B0 - B1 - B3;

            const int i0 = j - 3;
            const float* wf = s_swT + (c << 8) + tid;   // bank = lane
            float s = 0.0f;
            if ((unsigned)(i0    ) < 8u) s = fmaf(B0, wf[(i0    ) << 10], s);
            if ((unsigned)(i0 + 1) < 8u) s = fmaf(B1, wf[(i0 + 1) << 10], s);
            if ((unsigned)(i0 + 2) < 8u) s = fmaf(B2, wf[(i0 + 2) << 10], s);
            if ((unsigned)(i0 + 3) < 8u) s = fmaf(B3, wf[(i0 + 3) << 10], s);

            const float sil = __fdividef(n, 1.0f + __expf(-n));
            resp[c] = fmaf(W[c], sil, s);
        }

        *reinterpret_cast<float4*>(out + (size_t)row * NF + col) = res;
        cur = nxt;
    }
}

extern "C" void kernel_launch(void* const* d_in, const int* in_sizes, int n_in,
                              void* d_out, int out_size)
{
    const float* x    = (const float*)d_in[0];
    const float* lnw  = (const float*)d_in[1];
    const float* lnb  = (const float*)d_in[2];
    const float* sw   = (const float*)d_in[3];
    const float* bw   = (const float*)d_in[4];
    const float* grid = (const float*)d_in[5];
    float* out = (float*)d_out;

    kan_fused6<<<NBLOCKS, NTHREADS>>>(x, lnw, lnb, sw, bw, grid, out);
}